// round 5
// baseline (speedup 1.0000x reference)
#include <cuda_runtime.h>
#include <cstdint>

// ============================================================================
// AdditiveAttention: out = softmax_mask( sum_h tanh(Q@Wq + K@Wk) * wv ) @ V
// B=16, Q=128, K=128, D=512, H=512
//  kernel 0: reset task counter
//  kernel 1 (sgemm_proj): Qp/Kp projections, FFMA2 (fma.rn.f32x2) micro-kernel
//  kernel 2 (attn_kernel): persistent 148 blocks x 512 thr, atomic task queue,
//      task = (batch, 8 q-rows). 2 warps per q-row (64 k each), valid_len
//      group-skip, cross-warp softmax merge, AV bounded to ceil32(vlen).
// ============================================================================

#define BDIM 16
#define QDIM 128
#define KDIM 128
#define DDIM 512
#define HDIM 512
#define NTASKS 256          // 16 batches * 16 q-octets
#define NBLOCKS 148

typedef unsigned long long u64;

__device__ float g_Qp[BDIM * QDIM * HDIM];   // [b*128+q][h], 4 MB
__device__ float g_Kp[BDIM * KDIM * HDIM];   // [b*128+k][h], 4 MB
__device__ int   g_counter;

__device__ __forceinline__ float tanh_fast(float x) {
    float y;
    asm("tanh.approx.f32 %0, %1;" : "=f"(y) : "f"(x));
    return y;
}
__device__ __forceinline__ u64 pack2(float x, float y) {
    u64 r;
    asm("mov.b64 %0, {%1, %2};" : "=l"(r) : "f"(x), "f"(y));
    return r;
}
__device__ __forceinline__ void ffma2(u64& d, u64 a, u64 b) {
    asm("fma.rn.f32x2 %0, %1, %2, %0;" : "+l"(d) : "l"(a), "l"(b));
}

__global__ void reset_counter() { g_counter = 0; }

// ----------------------------------------------------------------------------
// Kernel 1: C[M,N] = A[M,K] * W[K,N]   M=2048, K=512, N=512
// 128x128 tile, BK=16, 256 threads, 8x8 micro-tile via 8x4 FFMA2 pairs.
// ----------------------------------------------------------------------------
__global__ __launch_bounds__(256, 1) void sgemm_proj(
    const float* __restrict__ Aq, const float* __restrict__ Ak,
    const float* __restrict__ Wq, const float* __restrict__ Wk)
{
    const int K = DDIM;
    const int N = HDIM;

    const float* A = blockIdx.z ? Ak : Aq;
    const float* W = blockIdx.z ? Wk : Wq;
    float* C = blockIdx.z ? g_Kp : g_Qp;

    __shared__ __align__(16) float As[16][132];   // transposed: As[k][m]
    __shared__ __align__(16) float Ws[16][128];   // Ws[k][n]

    const int tid = threadIdx.x;
    const int tx = tid & 15;
    const int ty = tid >> 4;
    const int m0 = blockIdx.y * 128;
    const int n0 = blockIdx.x * 128;

    const int arow = tid >> 2;
    const int ac   = (tid & 3) << 2;
    const int wk   = tid >> 5;
    const int wn   = (tid & 31) << 2;

    u64 acc2[8][4];
#pragma unroll
    for (int i = 0; i < 8; i++)
#pragma unroll
        for (int j = 0; j < 4; j++) acc2[i][j] = 0ull;

    float4 pa0, pa1, pw0, pw1;

    pa0 = *(const float4*)&A[(m0 + arow) * K + 0 + ac];
    pa1 = *(const float4*)&A[(m0 + arow + 64) * K + 0 + ac];
    pw0 = *(const float4*)&W[(0 + wk) * N + n0 + wn];
    pw1 = *(const float4*)&W[(0 + wk + 8) * N + n0 + wn];

    As[ac + 0][arow] = pa0.x; As[ac + 1][arow] = pa0.y;
    As[ac + 2][arow] = pa0.z; As[ac + 3][arow] = pa0.w;
    As[ac + 0][arow + 64] = pa1.x; As[ac + 1][arow + 64] = pa1.y;
    As[ac + 2][arow + 64] = pa1.z; As[ac + 3][arow + 64] = pa1.w;
    *(float4*)&Ws[wk][wn] = pw0;
    *(float4*)&Ws[wk + 8][wn] = pw1;
    __syncthreads();

    const int NIT = K / 16;   // 32
    for (int it = 0; it < NIT; ++it) {
        if (it + 1 < NIT) {
            const int kt = (it + 1) * 16;
            pa0 = *(const float4*)&A[(m0 + arow) * K + kt + ac];
            pa1 = *(const float4*)&A[(m0 + arow + 64) * K + kt + ac];
            pw0 = *(const float4*)&W[(kt + wk) * N + n0 + wn];
            pw1 = *(const float4*)&W[(kt + wk + 8) * N + n0 + wn];
        }
#pragma unroll
        for (int kk = 0; kk < 16; ++kk) {
            float a[8];
            *(float4*)&a[0] = *(const float4*)&As[kk][ty * 8];
            *(float4*)&a[4] = *(const float4*)&As[kk][ty * 8 + 4];
            u64 b2[4];
            const ulonglong2 bl0 = *(const ulonglong2*)&Ws[kk][tx * 8];
            const ulonglong2 bl1 = *(const ulonglong2*)&Ws[kk][tx * 8 + 4];
            b2[0] = bl0.x; b2[1] = bl0.y; b2[2] = bl1.x; b2[3] = bl1.y;
            u64 a2[8];
#pragma unroll
            for (int i = 0; i < 8; i++) a2[i] = pack2(a[i], a[i]);
#pragma unroll
            for (int i = 0; i < 8; i++)
#pragma unroll
                for (int j = 0; j < 4; j++)
                    ffma2(acc2[i][j], a2[i], b2[j]);
        }
        __syncthreads();
        if (it + 1 < NIT) {
            As[ac + 0][arow] = pa0.x; As[ac + 1][arow] = pa0.y;
            As[ac + 2][arow] = pa0.z; As[ac + 3][arow] = pa0.w;
            As[ac + 0][arow + 64] = pa1.x; As[ac + 1][arow + 64] = pa1.y;
            As[ac + 2][arow + 64] = pa1.z; As[ac + 3][arow + 64] = pa1.w;
            *(float4*)&Ws[wk][wn] = pw0;
            *(float4*)&Ws[wk + 8][wn] = pw1;
            __syncthreads();
        }
    }

#pragma unroll
    for (int i = 0; i < 8; i++) {
        u64* crow = (u64*)&C[(m0 + ty * 8 + i) * N + n0 + tx * 8];
#pragma unroll
        for (int j = 0; j < 4; j++) crow[j] = acc2[i][j];
    }
}

// ----------------------------------------------------------------------------
// Kernel 2: persistent fused scores + masked softmax + attn@V
// 148 blocks x 512 threads. Task t: b = t>>4, q-rows [8*(t&15), +8).
// Warp w: row = w>>1, k-half w2 = w&1 covers k in [64*w2, 64*w2+64):
//   lane tk owns k = tk + 32*j + 64*w2, j in {0,1}. 32-k groups with
//   base >= vlen are skipped entirely (uniform branch).
// ----------------------------------------------------------------------------
#define HC 64
#define KS_STRIDE 68   // 68 % 32 == 4 -> conflict-free LDS.128 pattern
#define POOL_FLOATS (128 * KS_STRIDE + 8 * KS_STRIDE + HDIM)   // 9760 = 39KB

__global__ __launch_bounds__(512, 1) void attn_kernel(
    const float* __restrict__ values,
    const int* __restrict__ valid_lens,
    const float* __restrict__ wv,
    float* __restrict__ out)
{
    const int tid = threadIdx.x;
    const int tk  = tid & 31;
    const int w   = tid >> 5;         // 0..15
    const int row = w >> 1;           // 0..7  (q-row within task)
    const int w2  = w & 1;            // k-half

    __shared__ __align__(16) float pool[POOL_FLOATS];
    float (*Ks)[KS_STRIDE] = (float(*)[KS_STRIDE])&pool[0];                 // 128x68
    float (*Qs)[KS_STRIDE] = (float(*)[KS_STRIDE])&pool[128 * KS_STRIDE];   // 8x68
    float* wvs = &pool[136 * KS_STRIDE];                                    // 512
    float (*attnT)[12] = (float(*)[12])&pool[0];     // aliases Ks (dead after A)
    __shared__ float pm[8][2], ps[8][2];
    __shared__ int s_task;

    // wv resident for whole block lifetime
    if (tid < 128)
        *(float4*)&wvs[tid * 4] = *(const float4*)&wv[tid * 4];

    // loader coords
    const int kq_row = tid >> 4;      // 0..31 (Ks rows, 4 groups of 32)
    const int kq_c4  = tid & 15;      // float4 index within 64-float chunk
    const int q_row  = tid >> 4;      // 0..7 for tid<128
    const int q_c4   = tid & 15;

    for (;;) {
        if (tid == 0) s_task = atomicAdd(&g_counter, 1);
        __syncthreads();               // also protects smem from previous task
        const int t = s_task;
        if (t >= NTASKS) break;

        const int b  = t >> 4;
        const int q8 = t & 15;
        const int vlen = valid_lens[b];
        const int kmax = min(KDIM, (vlen + 31) & ~31);
        const bool act0 = (64 * w2      < vlen);   // k-group [64w2, +32)
        const bool act1 = (64 * w2 + 32 < vlen);   // k-group [64w2+32, +32)

        const float* Qp = g_Qp + (b * QDIM + q8 * 8) * HDIM;
        const float* Kp = g_Kp + b * KDIM * HDIM;

        float4 pk[4];
        float4 pq;

        // prefetch chunk 0
#pragma unroll
        for (int i = 0; i < 4; i++)
            if (kq_row + 32 * i < kmax)
                pk[i] = *(const float4*)&Kp[(kq_row + 32 * i) * HDIM + kq_c4 * 4];
        if (tid < 128)
            pq = *(const float4*)&Qp[q_row * HDIM + q_c4 * 4];

#pragma unroll
        for (int i = 0; i < 4; i++)
            if (kq_row + 32 * i < kmax)
                *(float4*)&Ks[kq_row + 32 * i][kq_c4 * 4] = pk[i];
        if (tid < 128)
            *(float4*)&Qs[q_row][q_c4 * 4] = pq;
        __syncthreads();

        float s0 = 0.0f, s1 = 0.0f;

        // ---------------- Phase A ----------------
        const int NCH = HDIM / HC;   // 8
        for (int hc = 0; hc < NCH; ++hc) {
            const int h0 = hc * HC;
            if (hc + 1 < NCH) {
                const int hn = h0 + HC;
#pragma unroll
                for (int i = 0; i < 4; i++)
                    if (kq_row + 32 * i < kmax)
                        pk[i] = *(const float4*)&Kp[(kq_row + 32 * i) * HDIM + hn + kq_c4 * 4];
                if (tid < 128)
                    pq = *(const float4*)&Qp[q_row * HDIM + hn + q_c4 * 4];
            }

            if (act0 || act1) {
#pragma unroll
                for (int h4 = 0; h4 < HC / 4; ++h4) {
                    const float4 w4 = *(const float4*)&wvs[h0 + h4 * 4];
                    const float4 qa = *(const float4*)&Qs[row][h4 * 4];
                    if (act0) {
                        const float4 kv = *(const float4*)&Ks[tk + 64 * w2][h4 * 4];
                        s0 = fmaf(tanh_fast(qa.x + kv.x), w4.x, s0);
                        s0 = fmaf(tanh_fast(qa.y + kv.y), w4.y, s0);
                        s0 = fmaf(tanh_fast(qa.z + kv.z), w4.z, s0);
                        s0 = fmaf(tanh_fast(qa.w + kv.w), w4.w, s0);
                    }
                    if (act1) {
                        const float4 kv = *(const float4*)&Ks[tk + 32 + 64 * w2][h4 * 4];
                        s1 = fmaf(tanh_fast(qa.x + kv.x), w4.x, s1);
                        s1 = fmaf(tanh_fast(qa.y + kv.y), w4.y, s1);
                        s1 = fmaf(tanh_fast(qa.z + kv.z), w4.z, s1);
                        s1 = fmaf(tanh_fast(qa.w + kv.w), w4.w, s1);
                    }
                }
            }
            __syncthreads();
            if (hc + 1 < NCH) {
#pragma unroll
                for (int i = 0; i < 4; i++)
                    if (kq_row + 32 * i < kmax)
                        *(float4*)&Ks[kq_row + 32 * i][kq_c4 * 4] = pk[i];
                if (tid < 128)
                    *(float4*)&Qs[q_row][q_c4 * 4] = pq;
                __syncthreads();
            }
        }

        // ---------------- masked softmax ----------------
        if (tk + 64 * w2      >= vlen) s0 = -1e6f;
        if (tk + 32 + 64 * w2 >= vlen) s1 = -1e6f;

        float m = fmaxf(s0, s1);
#pragma unroll
        for (int off = 16; off > 0; off >>= 1)
            m = fmaxf(m, __shfl_xor_sync(0xFFFFFFFFu, m, off));
        float e0 = __expf(s0 - m), e1 = __expf(s1 - m);
        float sum = e0 + e1;
#pragma unroll
        for (int off = 16; off > 0; off >>= 1)
            sum += __shfl_xor_sync(0xFFFFFFFFu, sum, off);
        if (tk == 0) { pm[row][w2] = m; ps[row][w2] = sum; }
        __syncthreads();

        const float m0p = pm[row][0], m1p = pm[row][1];
        const float mg = fmaxf(m0p, m1p);
        const float sg = ps[row][0] * __expf(m0p - mg) + ps[row][1] * __expf(m1p - mg);
        const float rs = __expf(pm[row][w2] - mg) / sg;   // rescale this warp's e's
        __syncthreads();   // pm/ps read done before attnT (pool) overwrite is fine; attnT != pm/ps but Ks alias needs sync before writes
        attnT[tk + 64 * w2][row]      = e0 * rs;
        attnT[tk + 32 + 64 * w2][row] = e1 * rs;
        __syncthreads();

        // ---------------- Phase B: out[8,512] = attn[8,kmax] @ V[kmax,512] ---
        const int d = tid;
        const float* Vb = values + b * KDIM * DDIM + d;
        float acc[8];
#pragma unroll
        for (int q = 0; q < 8; q++) acc[q] = 0.0f;

        for (int k = 0; k < kmax; ++k) {
            const float v = Vb[k * DDIM];
            float a[8];
            *(float4*)&a[0] = *(const float4*)&attnT[k][0];
            *(float4*)&a[4] = *(const float4*)&attnT[k][4];
#pragma unroll
            for (int q = 0; q < 8; q++)
                acc[q] = fmaf(a[q], v, acc[q]);
        }

        float* Ob = out + (b * QDIM + q8 * 8) * DDIM + d;
#pragma unroll
        for (int q = 0; q < 8; q++)
            Ob[q * DDIM] = acc[q];
    }
}

// ----------------------------------------------------------------------------
extern "C" void kernel_launch(void* const* d_in, const int* in_sizes, int n_in,
                              void* d_out, int out_size)
{
    const float* queries    = (const float*)d_in[0];
    const float* keys       = (const float*)d_in[1];
    const float* values     = (const float*)d_in[2];
    const int*   valid_lens = (const int*)d_in[3];
    const float* Wq         = (const float*)d_in[4];
    const float* Wk         = (const float*)d_in[5];
    const float* wv         = (const float*)d_in[6];
    float* out = (float*)d_out;

    reset_counter<<<1, 1>>>();
    sgemm_proj<<<dim3(4, 16, 2), 256>>>(queries, keys, Wq, Wk);
    attn_kernel<<<NBLOCKS, 512>>>(values, valid_lens, wv, out);
}